// round 3
// baseline (speedup 1.0000x reference)
#include <cuda_runtime.h>

#define NROWS 65536
#define DDIM 512
#define NUM_LABELS 512
#define NUM_DEMOG 4
#define NGROUP (NUM_LABELS * NUM_DEMOG)

// -------- scratch (device globals; no allocation allowed) --------
__device__ int    g_cnt[NGROUP];
__device__ int    g_off[NGROUP + 1];
__device__ int    g_cursor[NGROUP];
__device__ int    g_sorted[NROWS];
__device__ int    g_seg[NROWS];
__device__ double g_gm[NGROUP];
__device__ int    g_is64;
__device__ int    g_hist_done;
__device__ int    g_group_done;

// ================= k_init: zero counters + dtype detect =================
__global__ void k_init(const int* labels_raw) {
    int t = threadIdx.x;               // 1024 threads
    g_cnt[t]        = 0;
    g_cnt[t + 1024] = 0;
    if (t == 0) {
        // int64 labels in [0,512) => every odd int32 word (high word) is 0.
        int nz = 0;
        for (int i = 1; i < 64; i += 2) nz += (labels_raw[i] != 0);
        g_is64 = (nz == 0) ? 1 : 0;
        g_hist_done = 0;
        g_group_done = 0;
    }
}

__device__ __forceinline__ int load_idx_val(const void* p, int i, int is64) {
    if (is64) return (int)((const long long*)p)[i];
    return ((const int*)p)[i];
}

// ============ k_hist_scan: histogram; last CTA does the prefix scan ============
__global__ void __launch_bounds__(1024) k_hist_scan(const void* labels, const void* demog) {
    int i = blockIdx.x * 1024 + threadIdx.x;   // 64 blocks x 1024 = 65536 exactly
    int is64 = g_is64;
    int lab = load_idx_val(labels, i, is64);
    int dem = load_idx_val(demog, i, is64);
    int seg = dem * NUM_LABELS + lab;
    g_seg[i] = seg;
    atomicAdd(&g_cnt[seg], 1);

    __shared__ int s_last;
    __syncthreads();
    if (threadIdx.x == 0) {
        __threadfence();
        s_last = (atomicAdd(&g_hist_done, 1) == gridDim.x - 1) ? 1 : 0;
    }
    __syncthreads();
    if (!s_last) return;
    __threadfence();   // acquire: all g_cnt atomics visible

    // ---- shuffle-based exclusive scan over 2048 counts (2 per thread) ----
    int t = threadIdx.x;
    int lane = t & 31, warp = t >> 5;
    int a = g_cnt[2 * t];
    int b = g_cnt[2 * t + 1];
    int pair = a + b;
    int v = pair;
    #pragma unroll
    for (int d = 1; d < 32; d <<= 1) {
        int u = __shfl_up_sync(0xffffffffu, v, d);
        if (lane >= d) v += u;
    }
    __shared__ int wsum[32];
    if (lane == 31) wsum[warp] = v;
    __syncthreads();
    if (warp == 0) {
        int w = wsum[lane];
        int x = w;
        #pragma unroll
        for (int d = 1; d < 32; d <<= 1) {
            int u = __shfl_up_sync(0xffffffffu, x, d);
            if (lane >= d) x += u;
        }
        wsum[lane] = x - w;   // exclusive warp prefix
    }
    __syncthreads();
    int incl = v + wsum[warp];
    int excl = incl - pair;
    g_off[2 * t]        = excl;
    g_off[2 * t + 1]    = excl + a;
    g_cursor[2 * t]     = excl;
    g_cursor[2 * t + 1] = excl + a;
    if (t == 1023) g_off[2048] = incl;
}

// ================= k_scatter: group-sorted row index list =================
__global__ void __launch_bounds__(1024) k_scatter() {
    int i = blockIdx.x * 1024 + threadIdx.x;
    int seg = g_seg[i];
    int pos = atomicAdd(&g_cursor[seg], 1);
    g_sorted[pos] = i;
}

// ===== k_group: one CTA per group; last CTA computes the final loss =====
// grp_mean_dist = (sum||x||^2 - ||sum x||^2 / cnt) / cnt
#define ACC4(v) do {                                                  \
    acc.x += (v).x; acc.y += (v).y; acc.z += (v).z; acc.w += (v).w;   \
} while (0)
#define SSQ(v, s) do {                                                \
    (s) += (v).x * (v).x + (v).y * (v).y + (v).z * (v).z + (v).w * (v).w; \
} while (0)

__global__ void __launch_bounds__(128, 8) k_group(const float4* __restrict__ feats,
                                                  float* __restrict__ out) {
    int g = blockIdx.x;
    int t = threadIdx.x;   // thread t owns columns [4t, 4t+4)
    int start = g_off[g];
    int end   = g_off[g + 1];

    __shared__ int    sidx[128];
    __shared__ double red[128];
    __shared__ double red2[128];

    float4 acc = make_float4(0.f, 0.f, 0.f, 0.f);
    float ssq0 = 0.f, ssq1 = 0.f, ssq2 = 0.f, ssq3 = 0.f;
    float ssq4 = 0.f, ssq5 = 0.f, ssq6 = 0.f, ssq7 = 0.f;

    for (int base = start; base < end; base += 128) {
        int n = min(128, end - base);
        __syncthreads();
        if (t < n) sidx[t] = g_sorted[base + t];
        __syncthreads();

        int r = 0;
        for (; r + 8 <= n; r += 8) {
            // 8 independent named loads: all issued before any consumption.
            const float4* p0 = feats + ((size_t)sidx[r + 0] << 7) + t;
            const float4* p1 = feats + ((size_t)sidx[r + 1] << 7) + t;
            const float4* p2 = feats + ((size_t)sidx[r + 2] << 7) + t;
            const float4* p3 = feats + ((size_t)sidx[r + 3] << 7) + t;
            const float4* p4 = feats + ((size_t)sidx[r + 4] << 7) + t;
            const float4* p5 = feats + ((size_t)sidx[r + 5] << 7) + t;
            const float4* p6 = feats + ((size_t)sidx[r + 6] << 7) + t;
            const float4* p7 = feats + ((size_t)sidx[r + 7] << 7) + t;
            float4 a0 = *p0; float4 a1 = *p1; float4 a2 = *p2; float4 a3 = *p3;
            float4 a4 = *p4; float4 a5 = *p5; float4 a6 = *p6; float4 a7 = *p7;
            ACC4(a0); SSQ(a0, ssq0);
            ACC4(a1); SSQ(a1, ssq1);
            ACC4(a2); SSQ(a2, ssq2);
            ACC4(a3); SSQ(a3, ssq3);
            ACC4(a4); SSQ(a4, ssq4);
            ACC4(a5); SSQ(a5, ssq5);
            ACC4(a6); SSQ(a6, ssq6);
            ACC4(a7); SSQ(a7, ssq7);
        }
        if (r + 4 <= n) {
            const float4* p0 = feats + ((size_t)sidx[r + 0] << 7) + t;
            const float4* p1 = feats + ((size_t)sidx[r + 1] << 7) + t;
            const float4* p2 = feats + ((size_t)sidx[r + 2] << 7) + t;
            const float4* p3 = feats + ((size_t)sidx[r + 3] << 7) + t;
            float4 a0 = *p0; float4 a1 = *p1; float4 a2 = *p2; float4 a3 = *p3;
            ACC4(a0); SSQ(a0, ssq0);
            ACC4(a1); SSQ(a1, ssq1);
            ACC4(a2); SSQ(a2, ssq2);
            ACC4(a3); SSQ(a3, ssq3);
            r += 4;
        }
        for (; r < n; ++r) {
            float4 v = feats[((size_t)sidx[r] << 7) + t];
            ACC4(v); SSQ(v, ssq0);
        }
    }

    double nrm = (double)acc.x * acc.x + (double)acc.y * acc.y +
                 (double)acc.z * acc.z + (double)acc.w * acc.w;
    double ssq = ((double)ssq0 + (double)ssq1) + ((double)ssq2 + (double)ssq3) +
                 ((double)ssq4 + (double)ssq5) + ((double)ssq6 + (double)ssq7);

    __syncthreads();
    red[t]  = ssq;
    red2[t] = nrm;
    __syncthreads();
    #pragma unroll
    for (int s = 64; s > 0; s >>= 1) {
        if (t < s) { red[t] += red[t + s]; red2[t] += red2[t + s]; }
        __syncthreads();
    }
    if (t == 0) {
        int cnt = end - start;
        double denom = (cnt > 0) ? (double)cnt : 1.0;
        g_gm[g] = (red[0] - red2[0] / denom) / denom;
    }

    // ---- last-CTA-done: fused finalize ----
    __shared__ int s_last;
    if (t == 0) {
        __threadfence();
        s_last = (atomicAdd(&g_group_done, 1) == NGROUP - 1) ? 1 : 0;
    }
    __syncthreads();
    if (!s_last) return;
    __threadfence();   // acquire: all g_gm visible

    __shared__ double fsum[NUM_DEMOG][128];
    __shared__ int    fcnt[NUM_DEMOG][128];
    double lsum[NUM_DEMOG] = {0.0, 0.0, 0.0, 0.0};
    int    lcnt[NUM_DEMOG] = {0, 0, 0, 0};
    for (int gg = t; gg < NGROUP; gg += 128) {
        int c = g_off[gg + 1] - g_off[gg];
        if (c > 0) {
            int d = gg >> 9;   // / NUM_LABELS
            lsum[d] += g_gm[gg];
            lcnt[d] += 1;
        }
    }
    #pragma unroll
    for (int d = 0; d < NUM_DEMOG; ++d) { fsum[d][t] = lsum[d]; fcnt[d][t] = lcnt[d]; }
    __syncthreads();
    #pragma unroll
    for (int s = 64; s > 0; s >>= 1) {
        if (t < s) {
            #pragma unroll
            for (int d = 0; d < NUM_DEMOG; ++d) {
                fsum[d][t] += fsum[d][t + s];
                fcnt[d][t] += fcnt[d][t + s];
            }
        }
        __syncthreads();
    }
    if (t == 0) {
        double intra[NUM_DEMOG];
        double mu = 0.0;
        #pragma unroll
        for (int d = 0; d < NUM_DEMOG; ++d) {
            int np = fcnt[d][0] > 0 ? fcnt[d][0] : 1;
            intra[d] = fsum[d][0] / (double)np;
            mu += intra[d];
        }
        mu /= (double)NUM_DEMOG;
        double loss = 0.0;
        #pragma unroll
        for (int d = 0; d < NUM_DEMOG; ++d) loss += fabs(intra[d] - mu);
        loss /= (double)NUM_DEMOG;
        out[0] = (float)loss;
    }
}

extern "C" void kernel_launch(void* const* d_in, const int* in_sizes, int n_in,
                              void* d_out, int out_size) {
    const float* feats  = (const float*)d_in[0];
    const void*  labels = d_in[1];
    const void*  demog  = d_in[2];
    float* out = (float*)d_out;

    k_init<<<1, 1024>>>((const int*)labels);
    k_hist_scan<<<64, 1024>>>(labels, demog);
    k_scatter<<<64, 1024>>>();
    k_group<<<NGROUP, 128>>>((const float4*)feats, out);
}

// round 4
// speedup vs baseline: 1.0677x; 1.0677x over previous
#include <cuda_runtime.h>
#include <cstdint>

#define NROWS 65536
#define DDIM 512
#define NUM_LABELS 512
#define NUM_DEMOG 4
#define NGROUP (NUM_LABELS * NUM_DEMOG)

// -------- scratch (device globals; no allocation allowed) --------
__device__ int    g_cnt[NGROUP];
__device__ int    g_off[NGROUP + 1];
__device__ int    g_cursor[NGROUP];
__device__ int    g_sorted[NROWS];
__device__ int    g_seg[NROWS];
__device__ double g_gm[NGROUP];
__device__ int    g_is64;
__device__ int    g_hist_done;
__device__ int    g_group_done;

// ================= k_init: zero counters + dtype detect =================
__global__ void k_init(const int* labels_raw) {
    int t = threadIdx.x;               // 1024 threads
    g_cnt[t]        = 0;
    g_cnt[t + 1024] = 0;
    if (t == 0) {
        // int64 labels in [0,512) => every odd int32 word (high word) is 0.
        int nz = 0;
        for (int i = 1; i < 64; i += 2) nz += (labels_raw[i] != 0);
        g_is64 = (nz == 0) ? 1 : 0;
        g_hist_done = 0;
        g_group_done = 0;
    }
}

__device__ __forceinline__ int load_idx_val(const void* p, int i, int is64) {
    if (is64) return (int)((const long long*)p)[i];
    return ((const int*)p)[i];
}

// ============ k_hist_scan: histogram; last CTA does the prefix scan ============
__global__ void __launch_bounds__(1024) k_hist_scan(const void* labels, const void* demog) {
    int i = blockIdx.x * 1024 + threadIdx.x;   // 64 blocks x 1024 = 65536 exactly
    int is64 = g_is64;
    int lab = load_idx_val(labels, i, is64);
    int dem = load_idx_val(demog, i, is64);
    int seg = dem * NUM_LABELS + lab;
    g_seg[i] = seg;
    atomicAdd(&g_cnt[seg], 1);

    __shared__ int s_last;
    __syncthreads();
    if (threadIdx.x == 0) {
        __threadfence();
        s_last = (atomicAdd(&g_hist_done, 1) == gridDim.x - 1) ? 1 : 0;
    }
    __syncthreads();
    if (!s_last) return;
    __threadfence();   // acquire: all g_cnt atomics visible

    // ---- shuffle-based exclusive scan over 2048 counts (2 per thread) ----
    int t = threadIdx.x;
    int lane = t & 31, warp = t >> 5;
    int a = g_cnt[2 * t];
    int b = g_cnt[2 * t + 1];
    int pair = a + b;
    int v = pair;
    #pragma unroll
    for (int d = 1; d < 32; d <<= 1) {
        int u = __shfl_up_sync(0xffffffffu, v, d);
        if (lane >= d) v += u;
    }
    __shared__ int wsum[32];
    if (lane == 31) wsum[warp] = v;
    __syncthreads();
    if (warp == 0) {
        int w = wsum[lane];
        int x = w;
        #pragma unroll
        for (int d = 1; d < 32; d <<= 1) {
            int u = __shfl_up_sync(0xffffffffu, x, d);
            if (lane >= d) x += u;
        }
        wsum[lane] = x - w;   // exclusive warp prefix
    }
    __syncthreads();
    int incl = v + wsum[warp];
    int excl = incl - pair;
    g_off[2 * t]        = excl;
    g_off[2 * t + 1]    = excl + a;
    g_cursor[2 * t]     = excl;
    g_cursor[2 * t + 1] = excl + a;
    if (t == 1023) g_off[2048] = incl;
}

// ================= k_scatter: group-sorted row index list =================
__global__ void __launch_bounds__(1024) k_scatter() {
    int i = blockIdx.x * 1024 + threadIdx.x;
    int seg = g_seg[i];
    int pos = atomicAdd(&g_cursor[seg], 1);
    g_sorted[pos] = i;
}

// ---------------- cp.async helpers ----------------
__device__ __forceinline__ void cp_async16(uint32_t dst, const float* src) {
    asm volatile("cp.async.cg.shared.global [%0], [%1], 16;" :: "r"(dst), "l"(src));
}
__device__ __forceinline__ void cp_commit() {
    asm volatile("cp.async.commit_group;" ::: "memory");
}
__device__ __forceinline__ void cp_wait0() {
    asm volatile("cp.async.wait_group 0;" ::: "memory");
}
__device__ __forceinline__ void cp_wait1() {
    asm volatile("cp.async.wait_group 1;" ::: "memory");
}

// ===== k_group: one CTA per group; cp.async double-buffered row gather =====
// grp_mean_dist = (sum||x||^2 - ||sum x||^2 / cnt) / cnt
__global__ void __launch_bounds__(128) k_group(const float* __restrict__ feats,
                                               float* __restrict__ out) {
    // 2 batches x 8 rows x 512 floats = 32 KB ring buffer.
    __shared__ __align__(16) float s_buf[2][8][DDIM];
    __shared__ int    sidx[128];
    __shared__ double wred[8];

    int g = blockIdx.x;
    int t = threadIdx.x;   // thread t owns columns [4t, 4t+4)
    int start = g_off[g];
    int end   = g_off[g + 1];

    // Per-thread fixed lane offset in the smem ring (16 B per thread per row).
    uint32_t buf_base = (uint32_t)__cvta_generic_to_shared(&s_buf[0][0][0]) + (uint32_t)t * 16u;

    float4 acc = make_float4(0.f, 0.f, 0.f, 0.f);
    float ssq0 = 0.f, ssq1 = 0.f;

    for (int base = start; base < end; base += 128) {
        int n = min(128, end - base);
        __syncthreads();
        if (t < n) sidx[t] = g_sorted[base + t];
        __syncthreads();

        int nb = (n + 7) >> 3;   // batches of 8 rows

        // prologue: issue batches 0..min(nb,2)-1 (all commits are real)
        #pragma unroll
        for (int p = 0; p < 2; ++p) {
            if (p < nb) {
                int r0 = p * 8, re = min(r0 + 8, n);
                for (int r = r0; r < re; ++r) {
                    const float* src = feats + (((size_t)sidx[r]) << 9) + (t << 2);
                    cp_async16(buf_base + (uint32_t)((p & 1) * 8 + (r - r0)) * 2048u, src);
                }
                cp_commit();
            }
        }

        for (int b = 0; b < nb; ++b) {
            if (b == nb - 1) cp_wait0(); else cp_wait1();

            int r0 = b * 8, re = min(r0 + 8, n);
            const float* bp = &s_buf[b & 1][0][t << 2];
            for (int r = r0; r < re; ++r) {
                float4 v = *(const float4*)(bp + (size_t)(r - r0) * DDIM);
                acc.x += v.x; acc.y += v.y; acc.z += v.z; acc.w += v.w;
                float s = v.x * v.x + v.y * v.y + v.z * v.z + v.w * v.w;
                if ((r - r0) & 1) ssq1 += s; else ssq0 += s;
            }

            int nxt = b + 2;
            if (nxt < nb) {
                int q0 = nxt * 8, qe = min(q0 + 8, n);
                for (int r = q0; r < qe; ++r) {
                    const float* src = feats + (((size_t)sidx[r]) << 9) + (t << 2);
                    cp_async16(buf_base + (uint32_t)((nxt & 1) * 8 + (r - q0)) * 2048u, src);
                }
                cp_commit();
            }
        }
    }

    // ---- per-group reduction: warp shuffle + tiny smem combine ----
    double nrm = (double)acc.x * acc.x + (double)acc.y * acc.y +
                 (double)acc.z * acc.z + (double)acc.w * acc.w;
    double ssq = (double)ssq0 + (double)ssq1;
    unsigned full = 0xffffffffu;
    #pragma unroll
    for (int o = 16; o > 0; o >>= 1) {
        nrm += __shfl_down_sync(full, nrm, o);
        ssq += __shfl_down_sync(full, ssq, o);
    }
    int lane = t & 31, w = t >> 5;
    if (lane == 0) { wred[w] = ssq; wred[4 + w] = nrm; }
    __syncthreads();
    if (t == 0) {
        double ss = wred[0] + wred[1] + wred[2] + wred[3];
        double nn = wred[4] + wred[5] + wred[6] + wred[7];
        int cnt = end - start;
        double den = (cnt > 0) ? (double)cnt : 1.0;
        g_gm[g] = (ss - nn / den) / den;
    }

    // ---- last-CTA-done: fused finalize ----
    __shared__ int s_last;
    if (t == 0) {
        __threadfence();
        s_last = (atomicAdd(&g_group_done, 1) == NGROUP - 1) ? 1 : 0;
    }
    __syncthreads();
    if (!s_last) return;
    __threadfence();   // acquire: all g_gm visible

    // alias finalize scratch onto the (now dead) ring buffer
    double* fsum = (double*)&s_buf[0][0][0];                 // 4*128 doubles = 4 KB
    int*    fcnt = (int*)((char*)&s_buf[0][0][0] + 4096);    // 4*128 int    = 2 KB

    double lsum[NUM_DEMOG] = {0.0, 0.0, 0.0, 0.0};
    int    lcnt[NUM_DEMOG] = {0, 0, 0, 0};
    for (int gg = t; gg < NGROUP; gg += 128) {
        int c = g_off[gg + 1] - g_off[gg];
        if (c > 0) {
            int d = gg >> 9;   // / NUM_LABELS
            lsum[d] += g_gm[gg];
            lcnt[d] += 1;
        }
    }
    #pragma unroll
    for (int d = 0; d < NUM_DEMOG; ++d) {
        fsum[d * 128 + t] = lsum[d];
        fcnt[d * 128 + t] = lcnt[d];
    }
    __syncthreads();
    #pragma unroll
    for (int s = 64; s > 0; s >>= 1) {
        if (t < s) {
            #pragma unroll
            for (int d = 0; d < NUM_DEMOG; ++d) {
                fsum[d * 128 + t] += fsum[d * 128 + t + s];
                fcnt[d * 128 + t] += fcnt[d * 128 + t + s];
            }
        }
        __syncthreads();
    }
    if (t == 0) {
        double intra[NUM_DEMOG];
        double mu = 0.0;
        #pragma unroll
        for (int d = 0; d < NUM_DEMOG; ++d) {
            int np = fcnt[d * 128] > 0 ? fcnt[d * 128] : 1;
            intra[d] = fsum[d * 128] / (double)np;
            mu += intra[d];
        }
        mu /= (double)NUM_DEMOG;
        double loss = 0.0;
        #pragma unroll
        for (int d = 0; d < NUM_DEMOG; ++d) loss += fabs(intra[d] - mu);
        loss /= (double)NUM_DEMOG;
        out[0] = (float)loss;
    }
}

extern "C" void kernel_launch(void* const* d_in, const int* in_sizes, int n_in,
                              void* d_out, int out_size) {
    const float* feats  = (const float*)d_in[0];
    const void*  labels = d_in[1];
    const void*  demog  = d_in[2];
    float* out = (float*)d_out;

    k_init<<<1, 1024>>>((const int*)labels);
    k_hist_scan<<<64, 1024>>>(labels, demog);
    k_scatter<<<64, 1024>>>();
    k_group<<<NGROUP, 128>>>(feats, out);
}

// round 5
// speedup vs baseline: 1.0936x; 1.0242x over previous
#include <cuda_runtime.h>
#include <cstdint>

#define NROWS 65536
#define DDIM 512
#define NUM_LABELS 512
#define NUM_DEMOG 4
#define NGROUP (NUM_LABELS * NUM_DEMOG)

#define GRID_STREAM 444          /* 148 SMs x 3 CTAs: one wave */
#define CHUNK 148                /* rows per CTA (444*148 = 65712 >= 65536) */
#define BR 8                     /* rows per batch */
#define NB 4                     /* ring depth in batches */
#define CHUNK_PAD 152            /* ceil(148/8)*8 */
#define NBATCH 19                /* CHUNK_PAD / BR */
#define ROWB 2048                /* bytes per row */

// -------- scratch (device globals; no allocation allowed) --------
__device__ int    g_cnt[NGROUP];
__device__ int    g_off[NGROUP + 1];
__device__ int    g_cursor[NGROUP];
__device__ int    g_sorted[NROWS];
__device__ int    g_seg[NROWS];
__device__ int    g_seg_sorted[NROWS];
__device__ float4 g_sums4[NGROUP * (DDIM / 4)];   // 4 MB group vector sums
__device__ float  g_ssq[NGROUP];
__device__ double g_gm[NGROUP];
__device__ int    g_is64;
__device__ int    g_hist_done;
__device__ int    g_group_done;

// ========== k_init: zero 4MB sums + counters, detect dtype ==========
__global__ void __launch_bounds__(128) k_init(const int* labels_raw) {
    int bid = blockIdx.x, t = threadIdx.x;          // grid 2048 x 128
    g_sums4[bid * 128 + t] = make_float4(0.f, 0.f, 0.f, 0.f);
    if (bid < 16)              g_cnt[bid * 128 + t] = 0;
    else if (bid < 32)         g_ssq[(bid - 16) * 128 + t] = 0.f;
    if (bid == 0 && t == 0) {
        int nz = 0;
        for (int i = 1; i < 64; i += 2) nz += (labels_raw[i] != 0);
        g_is64 = (nz == 0) ? 1 : 0;
        g_hist_done = 0;
        g_group_done = 0;
    }
}

__device__ __forceinline__ int load_idx_val(const void* p, int i, int is64) {
    if (is64) return (int)((const long long*)p)[i];
    return ((const int*)p)[i];
}

// ===== k_hist_scan: histogram; last CTA does the prefix scan =====
__global__ void __launch_bounds__(1024) k_hist_scan(const void* labels, const void* demog) {
    int i = blockIdx.x * 1024 + threadIdx.x;
    int is64 = g_is64;
    int lab = load_idx_val(labels, i, is64);
    int dem = load_idx_val(demog, i, is64);
    int seg = dem * NUM_LABELS + lab;
    g_seg[i] = seg;
    atomicAdd(&g_cnt[seg], 1);

    __shared__ int s_last;
    __syncthreads();
    if (threadIdx.x == 0) {
        __threadfence();
        s_last = (atomicAdd(&g_hist_done, 1) == gridDim.x - 1) ? 1 : 0;
    }
    __syncthreads();
    if (!s_last) return;
    __threadfence();

    int t = threadIdx.x;
    int lane = t & 31, warp = t >> 5;
    int a = g_cnt[2 * t];
    int b = g_cnt[2 * t + 1];
    int pair = a + b;
    int v = pair;
    #pragma unroll
    for (int d = 1; d < 32; d <<= 1) {
        int u = __shfl_up_sync(0xffffffffu, v, d);
        if (lane >= d) v += u;
    }
    __shared__ int wsum[32];
    if (lane == 31) wsum[warp] = v;
    __syncthreads();
    if (warp == 0) {
        int w = wsum[lane];
        int x = w;
        #pragma unroll
        for (int d = 1; d < 32; d <<= 1) {
            int u = __shfl_up_sync(0xffffffffu, x, d);
            if (lane >= d) x += u;
        }
        wsum[lane] = x - w;
    }
    __syncthreads();
    int incl = v + wsum[warp];
    int excl = incl - pair;
    g_off[2 * t]        = excl;
    g_off[2 * t + 1]    = excl + a;
    g_cursor[2 * t]     = excl;
    g_cursor[2 * t + 1] = excl + a;
    if (t == 1023) g_off[2048] = incl;
}

// ===== k_scatter: group-sorted row index + seg lists =====
__global__ void __launch_bounds__(1024) k_scatter() {
    int i = blockIdx.x * 1024 + threadIdx.x;
    int seg = g_seg[i];
    int pos = atomicAdd(&g_cursor[seg], 1);
    g_sorted[pos] = i;
    g_seg_sorted[pos] = seg;
}

// ---------------- cp.async helpers ----------------
__device__ __forceinline__ void cp_async16(uint32_t dst, const float* src) {
    asm volatile("cp.async.cg.shared.global [%0], [%1], 16;" :: "r"(dst), "l"(src));
}
__device__ __forceinline__ void cp_commit() { asm volatile("cp.async.commit_group;" ::: "memory"); }
__device__ __forceinline__ void cp_wait0() { asm volatile("cp.async.wait_group 0;" ::: "memory"); }
__device__ __forceinline__ void cp_wait1() { asm volatile("cp.async.wait_group 1;" ::: "memory"); }
__device__ __forceinline__ void cp_wait2() { asm volatile("cp.async.wait_group 2;" ::: "memory"); }

// ===== k_stream: single-wave persistent gather over sorted order =====
// Each CTA streams CHUNK contiguous sorted rows; flushes per-group partial
// (sum vector, ssq) to global atomics at group boundaries.
extern "C" __global__ void __launch_bounds__(128) k_stream(const float* __restrict__ feats) {
    extern __shared__ __align__(16) char sm[];
    float* ring = (float*)sm;                                  // NB*BR*ROWB = 64 KB
    int*   sidx = (int*)(sm + NB * BR * ROWB);                 // CHUNK_PAD ints
    int*   sseg = sidx + CHUNK_PAD;                            // CHUNK_PAD ints

    int bid = blockIdx.x, t = threadIdx.x;
    int lo = bid * CHUNK;

    // cooperative load of this chunk's indices + segs (padded)
    for (int i = t; i < CHUNK_PAD; i += 128) {
        int gi = lo + i;
        if (i < CHUNK && gi < NROWS) {
            sidx[i] = g_sorted[gi];
            sseg[i] = g_seg_sorted[gi];
        } else {
            sidx[i] = 0;
            sseg[i] = -1;        // pad: loaded but never accumulated
        }
    }
    __syncthreads();

    uint32_t ring_base = (uint32_t)__cvta_generic_to_shared(ring) + (uint32_t)t * 16u;
    const float* fbase = feats + (t << 2);

    // prologue: issue batches 0..2
    #pragma unroll
    for (int p = 0; p < 3; ++p) {
        #pragma unroll
        for (int r = 0; r < BR; ++r) {
            const float* src = fbase + ((size_t)sidx[p * BR + r] << 9);
            cp_async16(ring_base + (uint32_t)((p & (NB - 1)) * BR + r) * ROWB, src);
        }
        cp_commit();
    }

    float4 acc = make_float4(0.f, 0.f, 0.f, 0.f);
    float  ssq = 0.f;
    int    cur = -1;
    int    lane = t & 31;

    for (int b = 0; b < NBATCH; ++b) {
        int k = NBATCH - 1 - b;
        if (k >= 2) cp_wait2(); else if (k == 1) cp_wait1(); else cp_wait0();

        const float* bp = ring + (size_t)((b & (NB - 1)) * BR) * (ROWB / 4) + (t << 2);
        #pragma unroll
        for (int r = 0; r < BR; ++r) {
            int i = b * BR + r;
            int sg = sseg[i];
            if (sg != cur) {
                if (cur >= 0) {
                    // flush (uniform across CTA): 4 coalesced atomics + warp-reduced ssq
                    float* dst = (float*)g_sums4 + ((size_t)cur << 9) + (t << 2);
                    atomicAdd(dst + 0, acc.x);
                    atomicAdd(dst + 1, acc.y);
                    atomicAdd(dst + 2, acc.z);
                    atomicAdd(dst + 3, acc.w);
                    float ws = ssq;
                    #pragma unroll
                    for (int o = 16; o > 0; o >>= 1)
                        ws += __shfl_down_sync(0xffffffffu, ws, o);
                    if (lane == 0) atomicAdd(&g_ssq[cur], ws);
                }
                acc = make_float4(0.f, 0.f, 0.f, 0.f);
                ssq = 0.f;
                cur = sg;
            }
            if (sg >= 0) {
                float4 v = *(const float4*)(bp + (size_t)r * DDIM);
                acc.x += v.x; acc.y += v.y; acc.z += v.z; acc.w += v.w;
                ssq += v.x * v.x + v.y * v.y + v.z * v.z + v.w * v.w;
            }
        }
        int nxt = b + 3;
        if (nxt < NBATCH) {
            #pragma unroll
            for (int r = 0; r < BR; ++r) {
                const float* src = fbase + ((size_t)sidx[nxt * BR + r] << 9);
                cp_async16(ring_base + (uint32_t)((nxt & (NB - 1)) * BR + r) * ROWB, src);
            }
            cp_commit();
        }
    }
    // final flush
    if (cur >= 0) {
        float* dst = (float*)g_sums4 + ((size_t)cur << 9) + (t << 2);
        atomicAdd(dst + 0, acc.x);
        atomicAdd(dst + 1, acc.y);
        atomicAdd(dst + 2, acc.z);
        atomicAdd(dst + 3, acc.w);
        float ws = ssq;
        #pragma unroll
        for (int o = 16; o > 0; o >>= 1)
            ws += __shfl_down_sync(0xffffffffu, ws, o);
        if (lane == 0) atomicAdd(&g_ssq[cur], ws);
    }
}

// ===== k_pass2: per-group gm from sums; last CTA fuses the finalize =====
__global__ void __launch_bounds__(128) k_pass2(float* __restrict__ out) {
    __shared__ double wred[4];
    int g = blockIdx.x, t = threadIdx.x;
    int lane = t & 31, w = t >> 5;

    float4 v = g_sums4[g * 128 + t];
    double nn = (double)v.x * v.x + (double)v.y * v.y +
                (double)v.z * v.z + (double)v.w * v.w;
    #pragma unroll
    for (int o = 16; o > 0; o >>= 1)
        nn += __shfl_down_sync(0xffffffffu, nn, o);
    if (lane == 0) wred[w] = nn;
    __syncthreads();
    if (t == 0) {
        double normsq = wred[0] + wred[1] + wred[2] + wred[3];
        int cnt = g_cnt[g];
        double den = (cnt > 0) ? (double)cnt : 1.0;
        g_gm[g] = ((double)g_ssq[g] - normsq / den) / den;
    }

    // ---- last-CTA-done: finalize ----
    __shared__ int s_last;
    if (t == 0) {
        __threadfence();
        s_last = (atomicAdd(&g_group_done, 1) == NGROUP - 1) ? 1 : 0;
    }
    __syncthreads();
    if (!s_last) return;
    __threadfence();

    __shared__ double fsum[NUM_DEMOG][128];
    __shared__ int    fcnt[NUM_DEMOG][128];
    double lsum[NUM_DEMOG] = {0.0, 0.0, 0.0, 0.0};
    int    lcnt[NUM_DEMOG] = {0, 0, 0, 0};
    for (int gg = t; gg < NGROUP; gg += 128) {
        if (g_cnt[gg] > 0) {
            int d = gg >> 9;
            lsum[d] += g_gm[gg];
            lcnt[d] += 1;
        }
    }
    #pragma unroll
    for (int d = 0; d < NUM_DEMOG; ++d) { fsum[d][t] = lsum[d]; fcnt[d][t] = lcnt[d]; }
    __syncthreads();
    #pragma unroll
    for (int s = 64; s > 0; s >>= 1) {
        if (t < s) {
            #pragma unroll
            for (int d = 0; d < NUM_DEMOG; ++d) {
                fsum[d][t] += fsum[d][t + s];
                fcnt[d][t] += fcnt[d][t + s];
            }
        }
        __syncthreads();
    }
    if (t == 0) {
        double intra[NUM_DEMOG];
        double mu = 0.0;
        #pragma unroll
        for (int d = 0; d < NUM_DEMOG; ++d) {
            int np = fcnt[d][0] > 0 ? fcnt[d][0] : 1;
            intra[d] = fsum[d][0] / (double)np;
            mu += intra[d];
        }
        mu /= (double)NUM_DEMOG;
        double loss = 0.0;
        #pragma unroll
        for (int d = 0; d < NUM_DEMOG; ++d) loss += fabs(intra[d] - mu);
        loss /= (double)NUM_DEMOG;
        out[0] = (float)loss;
    }
}

extern "C" void kernel_launch(void* const* d_in, const int* in_sizes, int n_in,
                              void* d_out, int out_size) {
    const float* feats  = (const float*)d_in[0];
    const void*  labels = d_in[1];
    const void*  demog  = d_in[2];
    float* out = (float*)d_out;

    const int smem_stream = NB * BR * ROWB + 2 * CHUNK_PAD * (int)sizeof(int) + 256;
    cudaFuncSetAttribute(k_stream, cudaFuncAttributeMaxDynamicSharedMemorySize, smem_stream);

    k_init<<<2048, 128>>>((const int*)labels);
    k_hist_scan<<<64, 1024>>>(labels, demog);
    k_scatter<<<64, 1024>>>();
    k_stream<<<GRID_STREAM, 128, smem_stream>>>(feats);
    k_pass2<<<NGROUP, 128>>>(out);
}